// round 12
// baseline (speedup 1.0000x reference)
#include <cuda_runtime.h>

#define NQ      12
#define NT      256         // threads per CTA
#define NR      16          // amplitudes per thread
#define NLAYERS 4
#define XP      18          // padded row pitch (u64): conflict-free scalar+vector access
#define XSZ     (NT * XP)   // u64 elements per exchange buffer
#define PHYS(n) ((n) + 2u * ((n) >> 4))   // (n>>4)*XP + (n&15)

typedef unsigned long long u64;

// ---- packed f32x2 helpers (re in lo 32 bits, im in hi 32 bits) ----
__device__ __forceinline__ u64 pack2(float lo, float hi) {
    u64 r; asm("mov.b64 %0, {%1, %2};" : "=l"(r) : "f"(lo), "f"(hi)); return r;
}
__device__ __forceinline__ void unpack2(u64 v, float& lo, float& hi) {
    asm("mov.b64 {%0, %1}, %2;" : "=f"(lo), "=f"(hi) : "l"(v));
}
__device__ __forceinline__ u64 swap2(u64 v) {
    u64 r;
    asm("{\n\t.reg .b32 l, h;\n\tmov.b64 {l, h}, %1;\n\tmov.b64 %0, {h, l};\n\t}"
        : "=l"(r) : "l"(v));
    return r;
}
__device__ __forceinline__ u64 ffma2(u64 a, u64 b, u64 c) {
    u64 r; asm("fma.rn.f32x2 %0, %1, %2, %3;" : "=l"(r) : "l"(a), "l"(b), "l"(c)); return r;
}
__device__ __forceinline__ u64 fmul2(u64 a, u64 b) {
    u64 r; asm("mul.rn.f32x2 %0, %1, %2;" : "=l"(r) : "l"(a), "l"(b)); return r;
}
__device__ __forceinline__ float2 cmul(float2 a, float2 b) {
    return make_float2(fmaf(-a.y, b.y, a.x * b.x), fmaf(a.y, b.x, a.x * b.y));
}

// ---- RY gate coefficients, preloaded into registers ----
struct RYC { u64 C, S, NS; };
__device__ __forceinline__ RYC load_ry(const u64* g) {
    RYC c; ulonglong2 cs = *(const ulonglong2*)g;   // C, S
    c.C = cs.x; c.S = cs.y; c.NS = g[2];
    return c;
}
// REAL RY gate on register bit P: 4 packed FMAs per pair, coeffs in registers.
template<int P>
__device__ __forceinline__ void gate_ry(u64* st, RYC c) {
#pragma unroll
    for (int k = 0; k < NR / 2; k++) {
        const int r0 = ((k >> P) << (P + 1)) | (k & ((1 << P) - 1));
        const int r1 = r0 | (1 << P);
        u64 m0 = st[r0], m1 = st[r1];
        st[r0] = ffma2(c.NS, m1, fmul2(c.C, m0));   // c*m0 - s*m1
        st[r1] = ffma2(c.C,  m1, fmul2(c.S, m0));   // s*m0 + c*m1
    }
}

// ======================= layouts & transposes =======================
// amp index n[11:0], wire q <-> bit (11-q). phys(n) = (n>>4)*XP + (n&15).
// Layout A: n = (t<<4)|r     wires 0..7 = t7..t0, 8..11 = r3..r0
// Layout C: n = ((t>>4)<<8)|(r<<4)|(t&15)
// Layout D: n = (r<<8)|t     wires 0..3 = r3..r0, 4..11 = t7..t0
// Double-buffer rule: CTA-wide round-trips alternate x0 (sweep exchanges) and
// x1 (cnot perms); one __syncthreads() per round-trip suffices.

#define ADDR_A(t, r) ((t) * XP + (r))
#define ADDR_C(t, r) (((((t) >> 4) << 4) | (r)) * XP + ((t) & 15))
#define ADDR_D(t, r) ((((r) << 4) | ((t) >> 4)) * XP + ((t) & 15))

__device__ __forceinline__ void storeA_vec(const u64* st, int t, u64* x) {
#pragma unroll
    for (int r = 0; r < NR; r += 2)
        *(ulonglong2*)&x[ADDR_A(t, r)] = make_ulonglong2(st[r], st[r + 1]);
}
__device__ __forceinline__ void loadA_vec(u64* st, int t, const u64* x) {
#pragma unroll
    for (int r = 0; r < NR; r += 2) {
        ulonglong2 v = *(const ulonglong2*)&x[ADDR_A(t, r)];
        st[r] = v.x; st[r + 1] = v.y;
    }
}

__device__ __forceinline__ void exch_A_to_C(u64* st, int t, u64* x) {   // warp-local
    storeA_vec(st, t, x);
    __syncwarp();
#pragma unroll
    for (int r = 0; r < NR; r++) st[r] = x[ADDR_C(t, r)];
    __syncwarp();
}
__device__ __forceinline__ void exch_C_to_A(u64* st, int t, u64* x) {   // warp-local
#pragma unroll
    for (int r = 0; r < NR; r++) x[ADDR_C(t, r)] = st[r];
    __syncwarp();
    loadA_vec(st, t, x);
    __syncwarp();
}
__device__ __forceinline__ void exch_C_to_D(u64* st, int t, u64* x) {   // CTA, 1 bar
#pragma unroll
    for (int r = 0; r < NR; r++) x[ADDR_C(t, r)] = st[r];
    __syncthreads();
#pragma unroll
    for (int r = 0; r < NR; r++) st[r] = x[ADDR_D(t, r)];
}
__device__ __forceinline__ void exch_D_to_C(u64* st, int t, u64* x) {   // CTA, 1 bar
#pragma unroll
    for (int r = 0; r < NR; r++) x[ADDR_D(t, r)] = st[r];
    __syncthreads();
#pragma unroll
    for (int r = 0; r < NR; r++) st[r] = x[ADDR_C(t, r)];
    __syncwarp();   // reads are own-slice; order before this warp's next WL write
}

// ======================= RY-only sweeps with pipelined coeff loads =======================
__device__ __forceinline__ void sweep_A_to_D(u64* st, const u64* G, int t, u64* x) {
    RYC a0 = load_ry(G + 8*4), a1 = load_ry(G + 9*4),
        a2 = load_ry(G + 10*4), a3 = load_ry(G + 11*4);
    gate_ry<3>(st, a0);  gate_ry<2>(st, a1);  gate_ry<1>(st, a2);  gate_ry<0>(st, a3);
    RYC b0 = load_ry(G + 4*4), b1 = load_ry(G + 5*4),
        b2 = load_ry(G + 6*4), b3 = load_ry(G + 7*4);     // hide behind exchange
    exch_A_to_C(st, t, x);
    gate_ry<3>(st, b0);  gate_ry<2>(st, b1);  gate_ry<1>(st, b2);  gate_ry<0>(st, b3);
    RYC c0 = load_ry(G + 0*4), c1 = load_ry(G + 1*4),
        c2 = load_ry(G + 2*4), c3 = load_ry(G + 3*4);     // hide behind barrier
    exch_C_to_D(st, t, x);
    gate_ry<3>(st, c0);  gate_ry<2>(st, c1);  gate_ry<1>(st, c2);  gate_ry<0>(st, c3);
}
__device__ __forceinline__ void sweep_D_to_A(u64* st, const u64* G, int t, u64* x) {
    RYC a0 = load_ry(G + 0*4), a1 = load_ry(G + 1*4),
        a2 = load_ry(G + 2*4), a3 = load_ry(G + 3*4);
    gate_ry<3>(st, a0);  gate_ry<2>(st, a1);  gate_ry<1>(st, a2);  gate_ry<0>(st, a3);
    RYC b0 = load_ry(G + 4*4), b1 = load_ry(G + 5*4),
        b2 = load_ry(G + 6*4), b3 = load_ry(G + 7*4);     // hide behind barrier
    exch_D_to_C(st, t, x);
    gate_ry<3>(st, b0);  gate_ry<2>(st, b1);  gate_ry<1>(st, b2);  gate_ry<0>(st, b3);
    RYC c0 = load_ry(G + 8*4), c1 = load_ry(G + 9*4),
        c2 = load_ry(G + 10*4), c3 = load_ry(G + 11*4);   // hide behind exchange
    exch_C_to_A(st, t, x);
    gate_ry<3>(st, c0);  gate_ry<2>(st, c1);  gate_ry<1>(st, c2);  gate_ry<0>(st, c3);
}

// ======================= global diagonal application (tree-reduced phase) =======================
__device__ __forceinline__ void diag_A(u64* st, int t, const float2 (*P)[2]) {
    float2 p01 = cmul(P[0][(t >> 7) & 1], P[1][(t >> 6) & 1]);
    float2 p23 = cmul(P[2][(t >> 5) & 1], P[3][(t >> 4) & 1]);
    float2 p45 = cmul(P[4][(t >> 3) & 1], P[5][(t >> 2) & 1]);
    float2 p67 = cmul(P[6][(t >> 1) & 1], P[7][t & 1]);
    float2 ph  = cmul(cmul(p01, p23), cmul(p45, p67));
    u64 Ah[4], Bh[4], Al[4], Bl[4];
#pragma unroll
    for (int i = 0; i < 4; i++) {
        float2 hi = cmul(ph, cmul(P[8][(i >> 1) & 1], P[9][i & 1]));
        float2 lo = cmul(P[10][(i >> 1) & 1], P[11][i & 1]);
        Ah[i] = pack2(hi.x, hi.x);  Bh[i] = pack2(-hi.y, hi.y);
        Al[i] = pack2(lo.x, lo.x);  Bl[i] = pack2(-lo.y, lo.y);
    }
#pragma unroll
    for (int r = 0; r < NR; r++) {
        u64 a = st[r];
        a = ffma2(Bh[r >> 2], swap2(a), fmul2(Ah[r >> 2], a));
        a = ffma2(Bl[r & 3],  swap2(a), fmul2(Al[r & 3],  a));
        st[r] = a;
    }
}
__device__ __forceinline__ void diag_D(u64* st, int t, const float2 (*P)[2]) {
    float2 p01 = cmul(P[4][(t >> 7) & 1], P[5][(t >> 6) & 1]);
    float2 p23 = cmul(P[6][(t >> 5) & 1], P[7][(t >> 4) & 1]);
    float2 p45 = cmul(P[8][(t >> 3) & 1], P[9][(t >> 2) & 1]);
    float2 p67 = cmul(P[10][(t >> 1) & 1], P[11][t & 1]);
    float2 ph  = cmul(cmul(p01, p23), cmul(p45, p67));
    u64 Ah[4], Bh[4], Al[4], Bl[4];
#pragma unroll
    for (int i = 0; i < 4; i++) {
        float2 hi = cmul(ph, cmul(P[0][(i >> 1) & 1], P[1][i & 1]));
        float2 lo = cmul(P[2][(i >> 1) & 1], P[3][i & 1]);
        Ah[i] = pack2(hi.x, hi.x);  Bh[i] = pack2(-hi.y, hi.y);
        Al[i] = pack2(lo.x, lo.x);  Bl[i] = pack2(-lo.y, lo.y);
    }
#pragma unroll
    for (int r = 0; r < NR; r++) {
        u64 a = st[r];
        a = ffma2(Bh[r >> 2], swap2(a), fmul2(Ah[r >> 2], a));
        a = ffma2(Bl[r & 3],  swap2(a), fmul2(Al[r & 3],  a));
        st[r] = a;
    }
}

// ======================= batched CNOT ring (smem unit-image basis) =======================
// U = images of the 12 n-bit unit vectors under M = T0∘...∘T11 (reverse ring order).
// Index math hoisted BEFORE the stores so the LDS+XOR chain hides behind the barrier.
template<bool LAYOUT_A>
__device__ __forceinline__ void cnotx(u64* st, int t, u64* x, const unsigned* U) {
    // thread-bit images: LAYOUT_A -> n-bits 4..11, LAYOUT_D -> n-bits 0..7
    uint4 ua = *(const uint4*)(U + (LAYOUT_A ? 4 : 0));
    uint4 ub = *(const uint4*)(U + (LAYOUT_A ? 8 : 4));
    uint4 ur = *(const uint4*)(U + (LAYOUT_A ? 0 : 8));  // reg-bit images
    unsigned v0 = 0;
    if (t & 1)   v0 ^= ua.x;
    if (t & 2)   v0 ^= ua.y;
    if (t & 4)   v0 ^= ua.z;
    if (t & 8)   v0 ^= ua.w;
    if (t & 16)  v0 ^= ub.x;
    if (t & 32)  v0 ^= ub.y;
    if (t & 64)  v0 ^= ub.z;
    if (t & 128) v0 ^= ub.w;
    if (LAYOUT_A) {
        storeA_vec(st, t, x);     // phys(t<<4|r) = t*XP + r: contiguous, 128-bit
    } else {
#pragma unroll
        for (int r = 0; r < NR; r++) {
            unsigned n = ((unsigned)r << 8) | (unsigned)t;
            x[PHYS(n)] = st[r];
        }
    }
    __syncthreads();
#pragma unroll
    for (int r = 0; r < NR; r++) {            // r compile-time -> constant-folded XOR tree
        unsigned m = v0;
        if (r & 8) m ^= ur.w;
        if (r & 4) m ^= ur.z;
        if (r & 2) m ^= ur.y;
        if (r & 1) m ^= ur.x;
        st[r] = x[PHYS(m)];
    }
}

// GF(2) ring transform (reverse order), setup threads only.
__device__ __forceinline__ unsigned ring_map(unsigned v, unsigned mask) {
#pragma unroll
    for (int k = NQ - 1; k >= 0; k--) {
        if (mask & (1u << k)) {
            const int cb = 11 - k;
            const int tb = 11 - ((k + 1) % NQ);
            v ^= ((v >> cb) & 1u) << tb;
        }
    }
    return v;
}

__device__ __forceinline__ float wred(float v) {
#pragma unroll
    for (int o = 16; o; o >>= 1) v += __shfl_xor_sync(0xFFFFFFFFu, v, o);
    return v;
}

__global__ void __launch_bounds__(NT)
qsim_kernel(const float* __restrict__ x,       // (B, 12)
            const float* __restrict__ w,       // (4, 12, 3)
            const float* __restrict__ ent,     // (4, 12)
            float* __restrict__ out)           // (B, 12)
{
    extern __shared__ __align__(16) u64 dsm[];       // 2 exchange buffers (dynamic)
    u64* x0 = dsm;                                    // sweep exchanges + warp-local
    u64* x1 = dsm + XSZ;                              // cnot permutations

    __shared__ __align__(16) u64 Usm[48 * 4];         // RY coeffs: C,S,NS,pad per gate
    __shared__ float2 Phs1[48][2];                    // RZ(phi) phases per gate per bit
    __shared__ float2 Phs2[48][2];                    // RZ(omega) phases per gate per bit
    __shared__ float red[(NT / 32) * NQ];
    __shared__ float2 encV[NQ][2];                    // encoding amps w/ layer-0 D1 folded
    __shared__ unsigned maskbits[NLAYERS];
    __shared__ __align__(16) unsigned units_sm[NLAYERS][16];  // bit images (12 used)

    const int b    = blockIdx.x;
    const int t    = threadIdx.x;
    const int lane = t & 31;
    const int wid  = t >> 5;

    // ---- precompute gates/phases/masks (parallel across threads) ----
    if (t < 64) {
        const float PI = 3.14159265358979323846f;
        if (t < NQ) {
            // encoding on wire t: column 0 of RZ(x^2 pi) RY(x pi), times layer-0 RZ(phi)
            float xv = __ldg(&x[b * NQ + t]);
            float s, c;  sincosf(0.5f * PI * xv, &s, &c);
            float sh, ch; sincosf(0.5f * PI * xv * xv, &sh, &ch);
            float2 a0 = make_float2( c * ch, -c * sh);
            float2 a1 = make_float2( s * ch,  s * sh);
            float pf = __ldg(&w[t * 3 + 0]);        // layer 0, wire t: phi
            float sp, cp; sincosf(0.5f * pf, &sp, &cp);
            encV[t][0] = cmul(a0, make_float2(cp, -sp));
            encV[t][1] = cmul(a1, make_float2(cp,  sp));
        } else if (t < 60) {
            int gi = t - NQ;   // = l*12 + q
            float phi = __ldg(&w[gi * 3 + 0]);
            float th  = __ldg(&w[gi * 3 + 1]);
            float om  = __ldg(&w[gi * 3 + 2]);
            float s, c;  sincosf(0.5f * th, &s, &c);
            u64* g = &Usm[gi * 4];
            g[0] = pack2(c, c);  g[1] = pack2(s, s);  g[2] = pack2(-s, -s);
            float sp, cp; sincosf(0.5f * phi, &sp, &cp);
            Phs1[gi][0] = make_float2(cp, -sp);
            Phs1[gi][1] = make_float2(cp,  sp);
            float so, co; sincosf(0.5f * om, &so, &co);
            Phs2[gi][0] = make_float2(co, -so);
            Phs2[gi][1] = make_float2(co,  so);
        } else {
            int l = t - 60;    // t in [60,64): build maskbits[l]
            unsigned mm = 0;
#pragma unroll
            for (int i = 0; i < NQ; i++)
                mm |= (__ldg(&ent[l * NQ + i]) > 0.5f ? 1u : 0u) << i;
            maskbits[l] = mm;
        }
    }
    __syncthreads();

    // ---- ring-perm unit images (threads 64..111); published by the first
    // CTA barrier inside layer-0's sweep, consumed in the first cnotx ----
    if (t >= 64 && t < 64 + NLAYERS * NQ) {
        int idx = t - 64, l = idx / NQ, i = idx % NQ;
        units_sm[l][i] = ring_map(1u << i, maskbits[l]);
    }

    // ---- encoded state (incl. layer-0 RZ(phi) diagonal) is a PRODUCT state ----
    // Build directly in layout D: n = (r<<8)|t; wires 0..3 = r3..r0, wires 4..11 = t7..t0.
    u64 st[NR];
    {
        float2 q45 = cmul(encV[4][(t >> 7) & 1], encV[5][(t >> 6) & 1]);
        float2 q67 = cmul(encV[6][(t >> 5) & 1], encV[7][(t >> 4) & 1]);
        float2 q89 = cmul(encV[8][(t >> 3) & 1], encV[9][(t >> 2) & 1]);
        float2 qAB = cmul(encV[10][(t >> 1) & 1], encV[11][t & 1]);
        float2 cm  = cmul(cmul(q45, q67), cmul(q89, qAB));
        float2 p01[4], p23[4];
#pragma unroll
        for (int i = 0; i < 4; i++) {
            p01[i] = cmul(encV[0][(i >> 1) & 1], encV[1][i & 1]);
            p23[i] = cmul(encV[2][(i >> 1) & 1], encV[3][i & 1]);
        }
#pragma unroll
        for (int r = 0; r < NR; r++) {
            float2 a = cmul(cmul(p01[r >> 2], p23[r & 3]), cm);
            st[r] = pack2(a.x, a.y);
        }
    }

    // ---- layers: RY sweep, D2 diag, CNOT perm, D1 diag of next layer ----
    // CTA round-trips alternate x0 (in-sweep) and x1 (cnot); one barrier each.
    {
        sweep_D_to_A(st, Usm +  0 * 48, t, x0);         // layer 0 RYs
        diag_A(st, t, &Phs2[0]);                        // D2_0
        cnotx<true>(st, t, x1, units_sm[0]);
        diag_A(st, t, &Phs1[12]);                       // D1_1

        sweep_A_to_D(st, Usm +  1 * 48, t, x0);         // layer 1 RYs
        diag_D(st, t, &Phs2[12]);                       // D2_1
        cnotx<false>(st, t, x1, units_sm[1]);
        diag_D(st, t, &Phs1[24]);                       // D1_2

        sweep_D_to_A(st, Usm +  2 * 48, t, x0);         // layer 2 RYs
        diag_A(st, t, &Phs2[24]);                       // D2_2
        cnotx<true>(st, t, x1, units_sm[2]);
        diag_A(st, t, &Phs1[36]);                       // D1_3

        sweep_A_to_D(st, Usm +  3 * 48, t, x0);         // layer 3 RYs
        // D2_3 dropped: |amp|^2 is phase-invariant
        cnotx<false>(st, t, x1, units_sm[3]);
    }

    // ---- readout in layout D: wires 0..3 = r3..r0, 4..6 = warp bits, 7..11 = lane bits ----
    float psum = 0.f, a0 = 0.f, a1 = 0.f, a2 = 0.f, a3 = 0.f;
#pragma unroll
    for (int r = 0; r < NR; r++) {
        float re, im; unpack2(st[r], re, im);
        float p = fmaf(re, re, im * im);
        psum += p;
        a0 += (r & 8) ? -p : p;
        a1 += (r & 4) ? -p : p;
        a2 += (r & 2) ? -p : p;
        a3 += (r & 1) ? -p : p;
    }
    float ra0 = wred(a0), ra1 = wred(a1), ra2 = wred(a2), ra3 = wred(a3);
    float ps  = wred(psum);
    float s7  = wred((lane & 16) ? -psum : psum);
    float s8  = wred((lane &  8) ? -psum : psum);
    float s9  = wred((lane &  4) ? -psum : psum);
    float s10 = wred((lane &  2) ? -psum : psum);
    float s11 = wred((lane &  1) ? -psum : psum);
    if (lane == 0) {
        float* rw = &red[wid * NQ];
        rw[0] = ra0;  rw[1] = ra1;  rw[2] = ra2;  rw[3] = ra3;
        rw[4] = (wid & 4) ? -ps : ps;
        rw[5] = (wid & 2) ? -ps : ps;
        rw[6] = (wid & 1) ? -ps : ps;
        rw[7] = s7;  rw[8] = s8;  rw[9] = s9;  rw[10] = s10;  rw[11] = s11;
    }
    __syncthreads();

    if (t < NQ) {
        float s = 0.f;
#pragma unroll
        for (int wi = 0; wi < NT / 32; wi++) s += red[wi * NQ + t];
        out[b * NQ + t] = s;   // SCALE = 1
    }
}

extern "C" void kernel_launch(void* const* d_in, const int* in_sizes, int n_in,
                              void* d_out, int out_size)
{
    const float* x   = (const float*)d_in[0];   // (B, 12)
    const float* w   = (const float*)d_in[1];   // (4, 12, 3)
    const float* ent = (const float*)d_in[2];   // (4, 12)
    float* out = (float*)d_out;                 // (B, 12)

    const size_t shmem = 2 * XSZ * sizeof(u64);  // 73728 B dynamic
    cudaFuncSetAttribute((const void*)qsim_kernel,
                         cudaFuncAttributeMaxDynamicSharedMemorySize, (int)shmem);

    int B = in_sizes[0] / NQ;
    qsim_kernel<<<B, NT, shmem>>>(x, w, ent, out);
}

// round 13
// speedup vs baseline: 1.0964x; 1.0964x over previous
#include <cuda_runtime.h>

#define NQ      12
#define NT      256         // threads per CTA
#define NR      16          // amplitudes per thread
#define NLAYERS 4
#define XP      17          // padded row pitch (u64) -> conflict-free transposes
#define XSZ     (NT * XP)   // u64 elements per exchange buffer
#define PHYS(n) ((n) + ((n) >> 4))   // (n>>4)*XP + (n&15)

typedef unsigned long long u64;

// ---- packed f32x2 helpers (re in lo 32 bits, im in hi 32 bits) ----
__device__ __forceinline__ u64 pack2(float lo, float hi) {
    u64 r; asm("mov.b64 %0, {%1, %2};" : "=l"(r) : "f"(lo), "f"(hi)); return r;
}
__device__ __forceinline__ void unpack2(u64 v, float& lo, float& hi) {
    asm("mov.b64 {%0, %1}, %2;" : "=f"(lo), "=f"(hi) : "l"(v));
}
__device__ __forceinline__ u64 swap2(u64 v) {
    u64 r;
    asm("{\n\t.reg .b32 l, h;\n\tmov.b64 {l, h}, %1;\n\tmov.b64 %0, {h, l};\n\t}"
        : "=l"(r) : "l"(v));
    return r;
}
__device__ __forceinline__ u64 ffma2(u64 a, u64 b, u64 c) {
    u64 r; asm("fma.rn.f32x2 %0, %1, %2, %3;" : "=l"(r) : "l"(a), "l"(b), "l"(c)); return r;
}
__device__ __forceinline__ u64 fmul2(u64 a, u64 b) {
    u64 r; asm("mul.rn.f32x2 %0, %1, %2;" : "=l"(r) : "l"(a), "l"(b)); return r;
}
__device__ __forceinline__ float2 cmul(float2 a, float2 b) {
    return make_float2(fmaf(-a.y, b.y, a.x * b.x), fmaf(a.y, b.x, a.x * b.y));
}

// ---- REAL RY gate on register bit P: 4 packed FMAs per pair, no swaps ----
// coeffs per gate (4 u64, stride 4): [C=(c,c), S=(s,s), NS=(-s,-s), pad]
template<int P>
__device__ __forceinline__ void gate_ry(u64* st, const u64* g) {
    ulonglong2 cs = *(const ulonglong2*)(g);   // C, S
    u64 NS = g[2];
#pragma unroll
    for (int k = 0; k < NR / 2; k++) {
        const int r0 = ((k >> P) << (P + 1)) | (k & ((1 << P) - 1));
        const int r1 = r0 | (1 << P);
        u64 m0 = st[r0], m1 = st[r1];
        st[r0] = ffma2(NS,   m1, fmul2(cs.x, m0));   // c*m0 - s*m1
        st[r1] = ffma2(cs.x, m1, fmul2(cs.y, m0));   // s*m0 + c*m1
    }
}

// ======================= layouts & transposes =======================
// amp index n[11:0], wire q <-> bit (11-q). phys(n) = n + (n>>4).
// Layout A: n = (t<<4)|r     wires 0..7 = t7..t0, 8..11 = r3..r0
// Layout C: n = ((t>>4)<<8)|(r<<4)|(t&15)
// Layout D: n = (r<<8)|t     wires 0..3 = r3..r0, 4..11 = t7..t0
// Double-buffer rule: CTA-wide round-trips alternate x0 (sweep exchanges) and
// x1 (cnot perms); one __syncthreads() per round-trip suffices.

#define ADDR_A(t, r) ((t) * XP + (r))
#define ADDR_C(t, r) (((((t) >> 4) << 4) | (r)) * XP + ((t) & 15))
#define ADDR_D(t, r) ((((r) << 4) | ((t) >> 4)) * XP + ((t) & 15))

__device__ __forceinline__ void exch_A_to_C(u64* st, int t, u64* x) {   // warp-local
#pragma unroll
    for (int r = 0; r < NR; r++) x[ADDR_A(t, r)] = st[r];
    __syncwarp();
#pragma unroll
    for (int r = 0; r < NR; r++) st[r] = x[ADDR_C(t, r)];
    __syncwarp();
}
__device__ __forceinline__ void exch_C_to_A(u64* st, int t, u64* x) {   // warp-local
#pragma unroll
    for (int r = 0; r < NR; r++) x[ADDR_C(t, r)] = st[r];
    __syncwarp();
#pragma unroll
    for (int r = 0; r < NR; r++) st[r] = x[ADDR_A(t, r)];
    __syncwarp();
}
__device__ __forceinline__ void exch_C_to_D(u64* st, int t, u64* x) {   // CTA, 1 bar
#pragma unroll
    for (int r = 0; r < NR; r++) x[ADDR_C(t, r)] = st[r];
    __syncthreads();
#pragma unroll
    for (int r = 0; r < NR; r++) st[r] = x[ADDR_D(t, r)];
}
__device__ __forceinline__ void exch_D_to_C(u64* st, int t, u64* x) {   // CTA, 1 bar
#pragma unroll
    for (int r = 0; r < NR; r++) x[ADDR_D(t, r)] = st[r];
    __syncthreads();
#pragma unroll
    for (int r = 0; r < NR; r++) st[r] = x[ADDR_C(t, r)];
    __syncwarp();   // reads are own-slice; order before this warp's next WL write
}

// ======================= RY-only sweeps (phases pulled out) =======================
__device__ __forceinline__ void sweep_A_to_D(u64* st, const u64* G, int t, u64* x) {
    gate_ry<3>(st, G +  8 * 4);  gate_ry<2>(st, G +  9 * 4);
    gate_ry<1>(st, G + 10 * 4);  gate_ry<0>(st, G + 11 * 4);
    exch_A_to_C(st, t, x);
    gate_ry<3>(st, G +  4 * 4);  gate_ry<2>(st, G +  5 * 4);
    gate_ry<1>(st, G +  6 * 4);  gate_ry<0>(st, G +  7 * 4);
    exch_C_to_D(st, t, x);
    gate_ry<3>(st, G +  0 * 4);  gate_ry<2>(st, G +  1 * 4);
    gate_ry<1>(st, G +  2 * 4);  gate_ry<0>(st, G +  3 * 4);
}
__device__ __forceinline__ void sweep_D_to_A(u64* st, const u64* G, int t, u64* x) {
    gate_ry<3>(st, G +  0 * 4);  gate_ry<2>(st, G +  1 * 4);
    gate_ry<1>(st, G +  2 * 4);  gate_ry<0>(st, G +  3 * 4);
    exch_D_to_C(st, t, x);
    gate_ry<3>(st, G +  4 * 4);  gate_ry<2>(st, G +  5 * 4);
    gate_ry<1>(st, G +  6 * 4);  gate_ry<0>(st, G +  7 * 4);
    exch_C_to_A(st, t, x);
    gate_ry<3>(st, G +  8 * 4);  gate_ry<2>(st, G +  9 * 4);
    gate_ry<1>(st, G + 10 * 4);  gate_ry<0>(st, G + 11 * 4);
}

// ======================= global diagonal application (tree-reduced phase) =======================
__device__ __forceinline__ void diag_A(u64* st, int t, const float2 (*P)[2]) {
    float2 p01 = cmul(P[0][(t >> 7) & 1], P[1][(t >> 6) & 1]);
    float2 p23 = cmul(P[2][(t >> 5) & 1], P[3][(t >> 4) & 1]);
    float2 p45 = cmul(P[4][(t >> 3) & 1], P[5][(t >> 2) & 1]);
    float2 p67 = cmul(P[6][(t >> 1) & 1], P[7][t & 1]);
    float2 ph  = cmul(cmul(p01, p23), cmul(p45, p67));
    u64 Ah[4], Bh[4], Al[4], Bl[4];
#pragma unroll
    for (int i = 0; i < 4; i++) {
        float2 hi = cmul(ph, cmul(P[8][(i >> 1) & 1], P[9][i & 1]));
        float2 lo = cmul(P[10][(i >> 1) & 1], P[11][i & 1]);
        Ah[i] = pack2(hi.x, hi.x);  Bh[i] = pack2(-hi.y, hi.y);
        Al[i] = pack2(lo.x, lo.x);  Bl[i] = pack2(-lo.y, lo.y);
    }
#pragma unroll
    for (int r = 0; r < NR; r++) {
        u64 a = st[r];
        a = ffma2(Bh[r >> 2], swap2(a), fmul2(Ah[r >> 2], a));
        a = ffma2(Bl[r & 3],  swap2(a), fmul2(Al[r & 3],  a));
        st[r] = a;
    }
}
__device__ __forceinline__ void diag_D(u64* st, int t, const float2 (*P)[2]) {
    float2 p01 = cmul(P[4][(t >> 7) & 1], P[5][(t >> 6) & 1]);
    float2 p23 = cmul(P[6][(t >> 5) & 1], P[7][(t >> 4) & 1]);
    float2 p45 = cmul(P[8][(t >> 3) & 1], P[9][(t >> 2) & 1]);
    float2 p67 = cmul(P[10][(t >> 1) & 1], P[11][t & 1]);
    float2 ph  = cmul(cmul(p01, p23), cmul(p45, p67));
    u64 Ah[4], Bh[4], Al[4], Bl[4];
#pragma unroll
    for (int i = 0; i < 4; i++) {
        float2 hi = cmul(ph, cmul(P[0][(i >> 1) & 1], P[1][i & 1]));
        float2 lo = cmul(P[2][(i >> 1) & 1], P[3][i & 1]);
        Ah[i] = pack2(hi.x, hi.x);  Bh[i] = pack2(-hi.y, hi.y);
        Al[i] = pack2(lo.x, lo.x);  Bl[i] = pack2(-lo.y, lo.y);
    }
#pragma unroll
    for (int r = 0; r < NR; r++) {
        u64 a = st[r];
        a = ffma2(Bh[r >> 2], swap2(a), fmul2(Ah[r >> 2], a));
        a = ffma2(Bl[r & 3],  swap2(a), fmul2(Al[r & 3],  a));
        st[r] = a;
    }
}

// ======================= batched CNOT ring (smem unit-image basis) =======================
// U = images of the 12 n-bit unit vectors under M = T0∘...∘T11 (reverse ring order).
// v0 (thread base) computed BEFORE the stores (hides its LDS+XOR chain behind
// store issue + barrier); reg-bit images loaded after the barrier to cap pressure.
template<bool LAYOUT_A>
__device__ __forceinline__ void cnotx(u64* st, int t, u64* x, const unsigned* U) {
    // thread-bit images: LAYOUT_A -> n-bits 4..11, LAYOUT_D -> n-bits 0..7
    uint4 ua = *(const uint4*)(U + (LAYOUT_A ? 4 : 0));
    uint4 ub = *(const uint4*)(U + (LAYOUT_A ? 8 : 4));
    unsigned v0 = 0;
    if (t & 1)   v0 ^= ua.x;
    if (t & 2)   v0 ^= ua.y;
    if (t & 4)   v0 ^= ua.z;
    if (t & 8)   v0 ^= ua.w;
    if (t & 16)  v0 ^= ub.x;
    if (t & 32)  v0 ^= ub.y;
    if (t & 64)  v0 ^= ub.z;
    if (t & 128) v0 ^= ub.w;
#pragma unroll
    for (int r = 0; r < NR; r++) {
        unsigned n = LAYOUT_A ? (((unsigned)t << 4) | (unsigned)r)
                              : (((unsigned)r << 8) | (unsigned)t);
        x[PHYS(n)] = st[r];
    }
    __syncthreads();
    uint4 ur = *(const uint4*)(U + (LAYOUT_A ? 0 : 8));  // reg-bit images
#pragma unroll
    for (int r = 0; r < NR; r++) {            // r compile-time -> constant-folded XOR tree
        unsigned m = v0;
        if (r & 8) m ^= ur.w;
        if (r & 4) m ^= ur.z;
        if (r & 2) m ^= ur.y;
        if (r & 1) m ^= ur.x;
        st[r] = x[PHYS(m)];
    }
}

// GF(2) ring transform (reverse order), setup threads only.
__device__ __forceinline__ unsigned ring_map(unsigned v, unsigned mask) {
#pragma unroll
    for (int k = NQ - 1; k >= 0; k--) {
        if (mask & (1u << k)) {
            const int cb = 11 - k;
            const int tb = 11 - ((k + 1) % NQ);
            v ^= ((v >> cb) & 1u) << tb;
        }
    }
    return v;
}

__device__ __forceinline__ float wred(float v) {
#pragma unroll
    for (int o = 16; o; o >>= 1) v += __shfl_xor_sync(0xFFFFFFFFu, v, o);
    return v;
}

__global__ void __launch_bounds__(NT)
qsim_kernel(const float* __restrict__ x,       // (B, 12)
            const float* __restrict__ w,       // (4, 12, 3)
            const float* __restrict__ ent,     // (4, 12)
            float* __restrict__ out)           // (B, 12)
{
    extern __shared__ __align__(16) u64 dsm[];       // 2 exchange buffers (dynamic)
    u64* x0 = dsm;                                    // sweep exchanges + warp-local
    u64* x1 = dsm + XSZ;                              // cnot permutations

    __shared__ __align__(16) u64 Usm[48 * 4];         // RY coeffs: C,S,NS,pad per gate
    __shared__ float2 Phs1[48][2];                    // RZ(phi) phases per gate per bit
    __shared__ float2 Phs2[48][2];                    // RZ(omega) phases per gate per bit
    __shared__ float red[(NT / 32) * NQ];
    __shared__ float2 encV[NQ][2];                    // encoding amps w/ layer-0 D1 folded
    __shared__ unsigned maskbits[NLAYERS];
    __shared__ __align__(16) unsigned units_sm[NLAYERS][16];  // bit images (12 used)

    const int b    = blockIdx.x;
    const int t    = threadIdx.x;
    const int lane = t & 31;
    const int wid  = t >> 5;

    // ---- precompute gates/phases/masks (parallel across threads) ----
    if (t < 64) {
        const float PI = 3.14159265358979323846f;
        if (t < NQ) {
            // encoding on wire t: column 0 of RZ(x^2 pi) RY(x pi), times layer-0 RZ(phi)
            float xv = __ldg(&x[b * NQ + t]);
            float s, c;  sincosf(0.5f * PI * xv, &s, &c);
            float sh, ch; sincosf(0.5f * PI * xv * xv, &sh, &ch);
            float2 a0 = make_float2( c * ch, -c * sh);
            float2 a1 = make_float2( s * ch,  s * sh);
            float pf = __ldg(&w[t * 3 + 0]);        // layer 0, wire t: phi
            float sp, cp; sincosf(0.5f * pf, &sp, &cp);
            encV[t][0] = cmul(a0, make_float2(cp, -sp));
            encV[t][1] = cmul(a1, make_float2(cp,  sp));
        } else if (t < 60) {
            int gi = t - NQ;   // = l*12 + q
            float phi = __ldg(&w[gi * 3 + 0]);
            float th  = __ldg(&w[gi * 3 + 1]);
            float om  = __ldg(&w[gi * 3 + 2]);
            float s, c;  sincosf(0.5f * th, &s, &c);
            u64* g = &Usm[gi * 4];
            g[0] = pack2(c, c);  g[1] = pack2(s, s);  g[2] = pack2(-s, -s);
            float sp, cp; sincosf(0.5f * phi, &sp, &cp);
            Phs1[gi][0] = make_float2(cp, -sp);
            Phs1[gi][1] = make_float2(cp,  sp);
            float so, co; sincosf(0.5f * om, &so, &co);
            Phs2[gi][0] = make_float2(co, -so);
            Phs2[gi][1] = make_float2(co,  so);
        } else {
            int l = t - 60;    // t in [60,64): build maskbits[l]
            unsigned mm = 0;
#pragma unroll
            for (int i = 0; i < NQ; i++)
                mm |= (__ldg(&ent[l * NQ + i]) > 0.5f ? 1u : 0u) << i;
            maskbits[l] = mm;
        }
    }
    __syncthreads();

    // ---- ring-perm unit images (threads 64..111); published by the first
    // CTA barrier inside layer-0's sweep, consumed in the first cnotx ----
    if (t >= 64 && t < 64 + NLAYERS * NQ) {
        int idx = t - 64, l = idx / NQ, i = idx % NQ;
        units_sm[l][i] = ring_map(1u << i, maskbits[l]);
    }

    // ---- encoded state (incl. layer-0 RZ(phi) diagonal) is a PRODUCT state ----
    // Build directly in layout D: n = (r<<8)|t; wires 0..3 = r3..r0, wires 4..11 = t7..t0.
    u64 st[NR];
    {
        float2 q45 = cmul(encV[4][(t >> 7) & 1], encV[5][(t >> 6) & 1]);
        float2 q67 = cmul(encV[6][(t >> 5) & 1], encV[7][(t >> 4) & 1]);
        float2 q89 = cmul(encV[8][(t >> 3) & 1], encV[9][(t >> 2) & 1]);
        float2 qAB = cmul(encV[10][(t >> 1) & 1], encV[11][t & 1]);
        float2 cm  = cmul(cmul(q45, q67), cmul(q89, qAB));
        float2 p01[4], p23[4];
#pragma unroll
        for (int i = 0; i < 4; i++) {
            p01[i] = cmul(encV[0][(i >> 1) & 1], encV[1][i & 1]);
            p23[i] = cmul(encV[2][(i >> 1) & 1], encV[3][i & 1]);
        }
#pragma unroll
        for (int r = 0; r < NR; r++) {
            float2 a = cmul(cmul(p01[r >> 2], p23[r & 3]), cm);
            st[r] = pack2(a.x, a.y);
        }
    }

    // ---- layers: RY sweep, D2 diag, CNOT perm, D1 diag of next layer ----
    // CTA round-trips alternate x0 (in-sweep) and x1 (cnot); one barrier each.
    {
        sweep_D_to_A(st, Usm +  0 * 48, t, x0);         // layer 0 RYs
        diag_A(st, t, &Phs2[0]);                        // D2_0
        cnotx<true>(st, t, x1, units_sm[0]);
        diag_A(st, t, &Phs1[12]);                       // D1_1

        sweep_A_to_D(st, Usm +  1 * 48, t, x0);         // layer 1 RYs
        diag_D(st, t, &Phs2[12]);                       // D2_1
        cnotx<false>(st, t, x1, units_sm[1]);
        diag_D(st, t, &Phs1[24]);                       // D1_2

        sweep_D_to_A(st, Usm +  2 * 48, t, x0);         // layer 2 RYs
        diag_A(st, t, &Phs2[24]);                       // D2_2
        cnotx<true>(st, t, x1, units_sm[2]);
        diag_A(st, t, &Phs1[36]);                       // D1_3

        sweep_A_to_D(st, Usm +  3 * 48, t, x0);         // layer 3 RYs
        // D2_3 dropped: |amp|^2 is phase-invariant
        cnotx<false>(st, t, x1, units_sm[3]);
    }

    // ---- readout in layout D: wires 0..3 = r3..r0, 4..6 = warp bits, 7..11 = lane bits ----
    float psum = 0.f, a0 = 0.f, a1 = 0.f, a2 = 0.f, a3 = 0.f;
#pragma unroll
    for (int r = 0; r < NR; r++) {
        float re, im; unpack2(st[r], re, im);
        float p = fmaf(re, re, im * im);
        psum += p;
        a0 += (r & 8) ? -p : p;
        a1 += (r & 4) ? -p : p;
        a2 += (r & 2) ? -p : p;
        a3 += (r & 1) ? -p : p;
    }
    float ra0 = wred(a0), ra1 = wred(a1), ra2 = wred(a2), ra3 = wred(a3);
    float ps  = wred(psum);
    float s7  = wred((lane & 16) ? -psum : psum);
    float s8  = wred((lane &  8) ? -psum : psum);
    float s9  = wred((lane &  4) ? -psum : psum);
    float s10 = wred((lane &  2) ? -psum : psum);
    float s11 = wred((lane &  1) ? -psum : psum);
    if (lane == 0) {
        float* rw = &red[wid * NQ];
        rw[0] = ra0;  rw[1] = ra1;  rw[2] = ra2;  rw[3] = ra3;
        rw[4] = (wid & 4) ? -ps : ps;
        rw[5] = (wid & 2) ? -ps : ps;
        rw[6] = (wid & 1) ? -ps : ps;
        rw[7] = s7;  rw[8] = s8;  rw[9] = s9;  rw[10] = s10;  rw[11] = s11;
    }
    __syncthreads();

    if (t < NQ) {
        float s = 0.f;
#pragma unroll
        for (int wi = 0; wi < NT / 32; wi++) s += red[wi * NQ + t];
        out[b * NQ + t] = s;   // SCALE = 1
    }
}

extern "C" void kernel_launch(void* const* d_in, const int* in_sizes, int n_in,
                              void* d_out, int out_size)
{
    const float* x   = (const float*)d_in[0];   // (B, 12)
    const float* w   = (const float*)d_in[1];   // (4, 12, 3)
    const float* ent = (const float*)d_in[2];   // (4, 12)
    float* out = (float*)d_out;                 // (B, 12)

    const size_t shmem = 2 * XSZ * sizeof(u64);  // 69632 B dynamic
    cudaFuncSetAttribute((const void*)qsim_kernel,
                         cudaFuncAttributeMaxDynamicSharedMemorySize, (int)shmem);

    int B = in_sizes[0] / NQ;
    qsim_kernel<<<B, NT, shmem>>>(x, w, ent, out);
}